// round 12
// baseline (speedup 1.0000x reference)
#include <cuda_runtime.h>
#include <float.h>

#define NPTS 500
#define NP 8
#define NCOL 4000
#define NBLK 125

// ---------------- scratch (device globals) ----------------
__device__ int   g_inds[NCOL];
__device__ int   g_inds_tc[NCOL];
__device__ float g_expw[2 * NCOL];
__device__ float g_psum[1000];
__device__ float g_cf[NPTS * 128];
__device__ float g_imf[NPTS * 32];
__device__ float g_h1[NPTS * 64];
__device__ float g_hp[NPTS * 256];
__device__ float g_wps1T[128 * 256];
__device__ float g_wps2T[256 * 128];
__device__ float g_wc2T [64 * 128];
__device__ float g_wfc1T[256 * 64];
__device__ float g_wfc2T[160 * 64];
__device__ float g_wfcT [128 * 64];
// grid barrier: generation is MONOTONIC (replay-safe for odd barrier counts)
__device__ unsigned          g_cnt = 0;
__device__ volatile unsigned g_gen = 0;

__device__ __forceinline__ float lrelu(float x) { return x > 0.f ? x : 0.01f * x; }
__device__ __forceinline__ unsigned ordf(float f) {
    unsigned u = __float_as_uint(f);
    return (u & 0x80000000u) ? ~u : (u | 0x80000000u);
}
#define BARW(id) asm volatile("bar.sync %0, %1;" :: "r"(id), "r"(256) : "memory")

__device__ __forceinline__ void gbar() {
    __threadfence();
    __syncthreads();
    if (threadIdx.x == 0) {
        unsigned gen = g_gen;
        if (atomicAdd(&g_cnt, 1) == NBLK - 1) {
            g_cnt = 0;
            __threadfence();
            g_gen = gen + 1;
        } else {
            while (g_gen == gen) __nanosleep(32);
            __threadfence();
        }
    }
    __syncthreads();
}

// ================= kernel A: weight transposes (one 32x32 tile per block) ====
__global__ __launch_bounds__(256) void ktr(const float* __restrict__ wps2,
                                           const float* __restrict__ wc2,
                                           const float* __restrict__ wfc1,
                                           const float* __restrict__ wfc2,
                                           const float* __restrict__ wfc,
                                           const float* __restrict__ wps1) {
    __shared__ __align__(16) float S[32][33];
    int b = blockIdx.x, t = threadIdx.x;
    const float* src; float* dst; int Rr, Cc, tile;
    if      (b < 32)  { src = wps2; dst = g_wps2T; Rr = 128; Cc = 256; tile = b; }
    else if (b < 40)  { src = wc2;  dst = g_wc2T;  Rr = 128; Cc = 64;  tile = b - 32; }
    else if (b < 56)  { src = wfc1; dst = g_wfc1T; Rr = 64;  Cc = 256; tile = b - 40; }
    else if (b < 66)  { src = wfc2; dst = g_wfc2T; Rr = 64;  Cc = 160; tile = b - 56; }
    else if (b < 74)  { src = wfc;  dst = g_wfcT;  Rr = 64;  Cc = 128; tile = b - 66; }
    else              { src = wps1; dst = g_wps1T; Rr = 256; Cc = 128; tile = b - 74; }
    int tilesC = Cc / 32;
    int tr = (tile / tilesC) * 32, tc = (tile % tilesC) * 32;
    int r = t >> 3, q = t & 7;
    float4 v = *(const float4*)(src + (tr + r) * Cc + tc + q * 4);
    S[r][q * 4 + 0] = v.x; S[r][q * 4 + 1] = v.y; S[r][q * 4 + 2] = v.z; S[r][q * 4 + 3] = v.w;
    __syncthreads();
    float4 o;
    o.x = S[q * 4 + 0][r]; o.y = S[q * 4 + 1][r]; o.z = S[q * 4 + 2][r]; o.w = S[q * 4 + 3][r];
    *(float4*)(dst + (tc + r) * Rr + tr + q * 4) = o;
}

#define SMF 14720

// ================= kernel B: P1 (KNN || features+Hp) -> gbar -> P3 ===========
__global__ __launch_bounds__(512) void uber(
        const float* __restrict__ c,   const float* __restrict__ ct,
        const float* __restrict__ imf,
        const float* __restrict__ wp1, const float* __restrict__ bp1,
        const float* __restrict__ wp2, const float* __restrict__ bp2,
        const float* __restrict__ wc1, const float* __restrict__ bc1,
        const float* __restrict__ bps1, const float* __restrict__ bps2,
        const float* __restrict__ bc2,
        const float* __restrict__ bfc1, const float* __restrict__ bfc2,
        const float* __restrict__ bfc,
        float* __restrict__ out) {
    extern __shared__ __align__(16) float sm[];
    int t = threadIdx.x;
    int b = blockIdx.x;
    int p0 = b * 4;

    // ========================= P1 =========================
    if (t < 256) {
        // ---- KNN: 8 queries (warp/query), refs padded to 512 ----
        if (b <= 62) for (int i = t; i < 1536; i += 256) sm[i]        = (i < 1500) ? ct[i] : 1e18f;
        if (b >= 62) for (int i = t; i < 1536; i += 256) sm[1536 + i] = (i < 1500) ? c[i]  : 1e18f;
        BARW(1);

        int warp = t >> 5, lane = t & 31;
        int gw = b * 8 + warp;
        int dir = gw >= NPTS;
        int q = dir ? gw - NPTS : gw;
        const float* Qg = dir ? ct : c;
        float qx = __ldg(Qg + q * 3 + 0), qy = __ldg(Qg + q * 3 + 1), qz = __ldg(Qg + q * 3 + 2);
        float qq = qx * qx + qy * qy + qz * qz;

        const float* R = sm + (dir ? 1536 : 0);
        int j0 = lane * 16;
        float bd[8]; int bi[8];
#pragma unroll
        for (int k = 0; k < 8; k++) { bd[k] = FLT_MAX; bi[k] = 0x3fffffff; }

#pragma unroll
        for (int h8 = 0; h8 < 2; h8++) {
            float f[24];
            const float4* rp = (const float4*)(R + (j0 + h8 * 8) * 3);
#pragma unroll
            for (int v = 0; v < 6; v++) *(float4*)&f[v * 4] = rp[v];
#pragma unroll
            for (int jj = 0; jj < 8; jj++) {
                float rx = f[jj * 3 + 0], ry = f[jj * 3 + 1], rz = f[jj * 3 + 2];
                float d2 = qq - 2.f * (qx * rx + qy * ry + qz * rz) + (rx * rx + ry * ry + rz * rz);
                int j = j0 + h8 * 8 + jj;
                if (d2 < bd[7] || (d2 == bd[7] && j < bi[7])) {
                    bd[7] = d2; bi[7] = j;
#pragma unroll
                    for (int k = 7; k > 0; k--) {
                        if (bd[k] < bd[k - 1] || (bd[k] == bd[k - 1] && bi[k] < bi[k - 1])) {
                            float td = bd[k]; bd[k] = bd[k - 1]; bd[k - 1] = td;
                            int   ti = bi[k]; bi[k] = bi[k - 1]; bi[k - 1] = ti;
                        }
                    }
                }
            }
        }

        int* selS = (int*)(sm + 3072);
#pragma unroll
        for (int s = 0; s < NP; s++) {
            unsigned key = ordf(bd[0]);
            unsigned mk  = __reduce_min_sync(0xffffffffu, key);
            unsigned mask = __ballot_sync(0xffffffffu, key == mk);
            int owner = __ffs(mask) - 1;
            if (lane == owner) {
                selS[warp * 8 + s] = bi[0];
#pragma unroll
                for (int k = 0; k < 7; k++) { bd[k] = bd[k + 1]; bi[k] = bi[k + 1]; }
                bd[7] = FLT_MAX; bi[7] = 0x3fffffff;
            }
        }
        __syncwarp();

        int*   outi = dir ? g_inds_tc : g_inds;
        float* oute = dir ? (g_expw + NCOL) : g_expw;
        float e = 0.f;
        if (lane < NP) {
            int mi = selS[warp * 8 + lane];
            float dx = qx - R[mi * 3 + 0];
            float dy = qy - R[mi * 3 + 1];
            float dz = qz - R[mi * 3 + 2];
            e = expf(-sqrtf(dx * dx + dy * dy + dz * dz));
            outi[q * NP + lane] = mi;
            oute[q * NP + lane] = e;
        }
        if (lane < 8) {
            e += __shfl_xor_sync(0x000000ffu, e, 4);
            e += __shfl_xor_sync(0x000000ffu, e, 2);
            e += __shfl_xor_sync(0x000000ffu, e, 1);
            if (lane == 0) g_psum[gw] = e;
        }
    } else {
        // ---- features: 4 points (imf^T, H64, cf, h1, Hp) ----
        int t2 = t - 256;
        float* HS  = sm + 3200;           // [4][64]
        float* IS  = sm + 3456;           // [4][32]
        float* WC  = sm + 3584;           // [32][68]  wc1^T padded
        float* WT  = sm + 5760;           // [64][132] wp2^T padded; later Hp partials
        float* CFS = sm + 14208;          // [4][128]

        for (int e = t2; e < 2048; e += 256) {        // wp2 -> WT[k][r]
            float4 v = __ldg((const float4*)(wp2 + e * 4));
            int r = e >> 4, k0 = (e & 15) * 4;
            WT[(k0 + 0) * 132 + r] = v.x;
            WT[(k0 + 1) * 132 + r] = v.y;
            WT[(k0 + 2) * 132 + r] = v.z;
            WT[(k0 + 3) * 132 + r] = v.w;
        }
        for (int e = t2; e < 512; e += 256) {         // wc1 -> WC[k][r]
            float4 v = __ldg((const float4*)(wc1 + e * 4));
            int r = e >> 3, k0 = (e & 7) * 4;
            WC[(k0 + 0) * 68 + r] = v.x;
            WC[(k0 + 1) * 68 + r] = v.y;
            WC[(k0 + 2) * 68 + r] = v.z;
            WC[(k0 + 3) * 68 + r] = v.w;
        }
        if (t2 < 128) {
            int lp = t2 >> 5, chn = t2 & 31;
            float v = imf[chn * NPTS + (p0 + lp)];
            IS[lp * 32 + chn] = v;
            g_imf[(p0 + lp) * 32 + chn] = v;
        }
        {
            int lp = t2 >> 6, r = t2 & 63;
            int p = p0 + lp;
            float h = bp1[r] + wp1[r * 3 + 0] * c[p * 3 + 0] + wp1[r * 3 + 1] * c[p * 3 + 1]
                             + wp1[r * 3 + 2] * c[p * 3 + 2];
            HS[lp * 64 + r] = lrelu(h);
        }
        BARW(2);

        if (t2 < 128) {   // cf: thread = (rowquad rq, point pt)
            int rq = t2 & 31, pt = t2 >> 5;
            const float* x = HS + pt * 64;
            float4 a = {0.f, 0.f, 0.f, 0.f};
#pragma unroll 8
            for (int k = 0; k < 64; k++) {
                float4 w = *(float4*)&WT[k * 132 + rq * 4];
                float xv = x[k];
                a.x += w.x * xv; a.y += w.y * xv; a.z += w.z * xv; a.w += w.w * xv;
            }
            float4 bb = __ldg((const float4*)(bp2 + rq * 4));
            a.x += bb.x; a.y += bb.y; a.z += bb.z; a.w += bb.w;
            *(float4*)&g_cf[(p0 + pt) * 128 + rq * 4] = a;
            *(float4*)&CFS[pt * 128 + rq * 4] = a;
        } else if (t2 < 192) {  // h1
            int u = t2 - 128, rq = u & 15, pt = u >> 4;
            const float* xi = IS + pt * 32;
            float4 a = {0.f, 0.f, 0.f, 0.f};
#pragma unroll 8
            for (int k = 0; k < 32; k++) {
                float4 w = *(float4*)&WC[k * 68 + rq * 4];
                float xv = xi[k];
                a.x += w.x * xv; a.y += w.y * xv; a.z += w.z * xv; a.w += w.w * xv;
            }
            float4 bb = __ldg((const float4*)(bc1 + rq * 4));
            float4 o;
            o.x = lrelu(a.x + bb.x); o.y = lrelu(a.y + bb.y);
            o.z = lrelu(a.z + bb.z); o.w = lrelu(a.w + bb.w);
            *(float4*)&g_h1[(p0 + pt) * 64 + rq * 4] = o;
        }
        BARW(2);

        {   // Hp: 256 rows x 4 cols, K=128; 256 threads: rq=t2&63, ks=t2>>6 (4 x K=32)
            float* P = WT;     // alias, WT dead after cf
            int rq = t2 & 63, ks = t2 >> 6;
            float4 a[4] = {};
            const float* wp = g_wps1T + (ks * 32) * 256 + rq * 4;
#pragma unroll
            for (int kg = 0; kg < 8; kg++) {
                float xk[4][4];
#pragma unroll
                for (int cc = 0; cc < 4; cc++)
                    *(float4*)xk[cc] = *(float4*)&CFS[cc * 128 + ks * 32 + kg * 4];
#pragma unroll
                for (int j = 0; j < 4; j++) {
                    float4 w4 = *(const float4*)(wp + (kg * 4 + j) * 256);
#pragma unroll
                    for (int cc = 0; cc < 4; cc++) {
                        float x = xk[cc][j];
                        a[cc].x += w4.x * x; a[cc].y += w4.y * x; a[cc].z += w4.z * x; a[cc].w += w4.w * x;
                    }
                }
            }
#pragma unroll
            for (int cc = 0; cc < 4; cc++)
                *(float4*)&P[(ks * 4 + cc) * 256 + rq * 4] = a[cc];
            BARW(2);
            for (int o = t2; o < 1024; o += 256) {
                int r = o & 255, cc2 = o >> 8;
                float s = 0.f;
#pragma unroll
                for (int k2 = 0; k2 < 4; k2++) s += P[(k2 * 4 + cc2) * 256 + r];
                g_hp[(p0 + cc2) * 256 + r] = lrelu(s + bps1[r]);
            }
        }
    }
    gbar();

    // ========================= P3: denom + gathers + GEMM chain =========================
    {
        int*   I0  = (int*)(sm + 0);
        int*   I1  = (int*)(sm + 32);
        float* W0  = sm + 64;
        float* W1  = sm + 96;
        float* Ws0 = sm + 128;
        float* Ws1 = sm + 132;
        float* Hb  = sm + 136;    // [4][64]
        float* Hpb = sm + 392;    // [4][256]
        float* A1  = sm + 1416;   // [4][256]  low=Sf high=Cf
        float* A2  = sm + 2440;   // [4][160]  low=Sfp high=Im
        float* Z   = sm + 3080;   // [4][128]
        float* PA  = sm + 3592;   // 4096
        float* PB  = sm + 7688;   // 4096
        float* RED = sm + 12900;  // [2][16]

        int wg = t >> 8, ta = t & 255;

        // softmax denominators (all 512 threads)
        {
            float v0 = (t < 500) ? g_psum[t]       : 0.f;
            float v1 = (t < 500) ? g_psum[500 + t] : 0.f;
#pragma unroll
            for (int off = 16; off; off >>= 1) {
                v0 += __shfl_xor_sync(0xffffffffu, v0, off);
                v1 += __shfl_xor_sync(0xffffffffu, v1, off);
            }
            if ((t & 31) == 0) { RED[t >> 5] = v0; RED[32 + (t >> 5)] = v1; }
        }
        if (wg == 0) {
            if (ta < 32) {
                int e = p0 * NP + ta;
                I0[ta] = g_inds[e];    W0[ta] = g_expw[e];
                I1[ta] = g_inds_tc[e]; W1[ta] = g_expw[NCOL + e];
            } else if (ta < 64) {
                int tt = ta - 32;
                int col = tt >> 3, f = tt & 7;
                *(float4*)&A2[col * 160 + 128 + f * 4] = *(const float4*)&g_imf[(p0 + col) * 32 + f * 4];
            }
        } else {
            if (ta < 128) {
                int col = ta >> 5, f = ta & 31;
                *(float4*)&A1[col * 256 + 128 + f * 4] = *(const float4*)&g_cf[(p0 + col) * 128 + f * 4];
            }
        }
        __syncthreads();
        if (t == 0) {
            float s0 = 0.f, s1 = 0.f;
#pragma unroll
            for (int w = 0; w < 16; w++) { s0 += RED[w]; s1 += RED[32 + w]; }
            sm[13000] = 1.f / s0;
            sm[13001] = 1.f / s1;
        }
        __syncthreads();
        float inv0 = sm[13000], inv1 = sm[13001];

        if (wg == 0) {
            if (ta < 4) {
                float s = 0;
#pragma unroll
                for (int j = 0; j < 8; j++) s += W1[ta * 8 + j];
                Ws1[ta] = 0.125f * inv1 * s;
            }
            {
                int r = ta;
#pragma unroll
                for (int lp = 0; lp < 4; lp++) {
                    float s = 0;
#pragma unroll
                    for (int j = 0; j < 8; j++) s += W1[lp * 8 + j] * g_hp[I1[lp * 8 + j] * 256 + r];
                    Hpb[lp * 256 + r] = 0.125f * inv1 * s;
                }
            }
            BARW(1);
            {   // Y2: 128 rows, K=256
                int rq = ta & 31, ks = ta >> 5;
                float4 a[4] = {};
                const float* wp = g_wps2T + (ks * 32) * 128 + rq * 4;
#pragma unroll
                for (int kg = 0; kg < 8; kg++) {
                    float xk[4][4];
#pragma unroll
                    for (int cc = 0; cc < 4; cc++)
                        *(float4*)xk[cc] = *(float4*)&Hpb[cc * 256 + ks * 32 + kg * 4];
#pragma unroll
                    for (int j = 0; j < 4; j++) {
                        float4 w4 = *(const float4*)(wp + (kg * 4 + j) * 128);
#pragma unroll
                        for (int cc = 0; cc < 4; cc++) {
                            float x = xk[cc][j];
                            a[cc].x += w4.x * x; a[cc].y += w4.y * x; a[cc].z += w4.z * x; a[cc].w += w4.w * x;
                        }
                    }
                }
#pragma unroll
                for (int cc = 0; cc < 4; cc++)
                    *(float4*)&PA[(ks * 4 + cc) * 128 + rq * 4] = a[cc];
            }
            BARW(1);
            for (int o = ta; o < 512; o += 256) {
                int r = o & 127, cc = o >> 7;
                float s = 0;
#pragma unroll
                for (int ks = 0; ks < 8; ks++) s += PA[(ks * 4 + cc) * 128 + r];
                A2[cc * 160 + r] = s + bps2[r] * Ws1[cc];
            }
            BARW(1);
            {   // f2: 64 rows, K=160
                int rq = ta & 15, ks = ta >> 4;
                float4 a[4] = {};
                const float* wp = g_wfc2T + (ks * 10) * 64 + rq * 4;
#pragma unroll
                for (int k = 0; k < 10; k++) {
                    float4 w4 = *(const float4*)(wp + k * 64);
                    int kk = ks * 10 + k;
#pragma unroll
                    for (int cc = 0; cc < 4; cc++) {
                        float x = A2[cc * 160 + kk];
                        a[cc].x += w4.x * x; a[cc].y += w4.y * x; a[cc].z += w4.z * x; a[cc].w += w4.w * x;
                    }
                }
#pragma unroll
                for (int cc = 0; cc < 4; cc++)
                    *(float4*)&PA[(ks * 4 + cc) * 64 + rq * 4] = a[cc];
            }
            BARW(1);
            {
                int ch = ta & 63, cc = ta >> 6;
                float s = 0;
#pragma unroll
                for (int ks = 0; ks < 16; ks++) s += PA[(ks * 4 + cc) * 64 + ch];
                Z[cc * 128 + ch] = lrelu(s + bfc2[ch]);
            }
        } else {
            if (ta < 4) {
                float s = 0;
#pragma unroll
                for (int j = 0; j < 8; j++) s += W0[ta * 8 + j];
                Ws0[ta] = 0.125f * inv0 * s;
            }
            {
                int lp = ta >> 6, r = ta & 63;
                float s = 0;
#pragma unroll
                for (int j = 0; j < 8; j++) s += W0[lp * 8 + j] * g_h1[I0[lp * 8 + j] * 64 + r];
                Hb[lp * 64 + r] = 0.125f * inv0 * s;
            }
            BARW(2);
            {   // Y1: 128 rows, K=64
                int rq = ta & 31, ks = ta >> 5;
                float4 a[4] = {};
                const float* wp = g_wc2T + (ks * 8) * 128 + rq * 4;
#pragma unroll
                for (int kg = 0; kg < 2; kg++) {
                    float xk[4][4];
#pragma unroll
                    for (int cc = 0; cc < 4; cc++)
                        *(float4*)xk[cc] = *(float4*)&Hb[cc * 64 + ks * 8 + kg * 4];
#pragma unroll
                    for (int j = 0; j < 4; j++) {
                        float4 w4 = *(const float4*)(wp + (kg * 4 + j) * 128);
#pragma unroll
                        for (int cc = 0; cc < 4; cc++) {
                            float x = xk[cc][j];
                            a[cc].x += w4.x * x; a[cc].y += w4.y * x; a[cc].z += w4.z * x; a[cc].w += w4.w * x;
                        }
                    }
                }
#pragma unroll
                for (int cc = 0; cc < 4; cc++)
                    *(float4*)&PB[(ks * 4 + cc) * 128 + rq * 4] = a[cc];
            }
            BARW(2);
            for (int o = ta; o < 512; o += 256) {
                int r = o & 127, cc = o >> 7;
                float s = 0;
#pragma unroll
                for (int ks = 0; ks < 8; ks++) s += PB[(ks * 4 + cc) * 128 + r];
                A1[cc * 256 + r] = s + bc2[r] * Ws0[cc];
            }
            BARW(2);
            {   // f1: 64 rows, K=256
                int rq = ta & 15, ks = ta >> 4;
                float4 a[4] = {};
                const float* wp = g_wfc1T + (ks * 16) * 64 + rq * 4;
#pragma unroll
                for (int kg = 0; kg < 4; kg++) {
                    float xk[4][4];
#pragma unroll
                    for (int cc = 0; cc < 4; cc++)
                        *(float4*)xk[cc] = *(float4*)&A1[cc * 256 + ks * 16 + kg * 4];
#pragma unroll
                    for (int j = 0; j < 4; j++) {
                        float4 w4 = *(const float4*)(wp + (kg * 4 + j) * 64);
#pragma unroll
                        for (int cc = 0; cc < 4; cc++) {
                            float x = xk[cc][j];
                            a[cc].x += w4.x * x; a[cc].y += w4.y * x; a[cc].z += w4.z * x; a[cc].w += w4.w * x;
                        }
                    }
                }
#pragma unroll
                for (int cc = 0; cc < 4; cc++)
                    *(float4*)&PB[(ks * 4 + cc) * 64 + rq * 4] = a[cc];
            }
            BARW(2);
            {
                int ch = ta & 63, cc = ta >> 6;
                float s = 0;
#pragma unroll
                for (int ks = 0; ks < 16; ks++) s += PB[(ks * 4 + cc) * 64 + ch];
                Z[cc * 128 + 64 + ch] = lrelu(s + bfc1[ch]);
            }
        }
        __syncthreads();

        if (wg == 0) {
            {   // out: 64 rows, K=128
                int rq = ta & 15, ks = ta >> 4;
                float4 a[4] = {};
                const float* wp = g_wfcT + (ks * 8) * 64 + rq * 4;
#pragma unroll
                for (int kg = 0; kg < 2; kg++) {
                    float xk[4][4];
#pragma unroll
                    for (int cc = 0; cc < 4; cc++)
                        *(float4*)xk[cc] = *(float4*)&Z[cc * 128 + ks * 8 + kg * 4];
#pragma unroll
                    for (int j = 0; j < 4; j++) {
                        float4 w4 = *(const float4*)(wp + (kg * 4 + j) * 64);
#pragma unroll
                        for (int cc = 0; cc < 4; cc++) {
                            float x = xk[cc][j];
                            a[cc].x += w4.x * x; a[cc].y += w4.y * x; a[cc].z += w4.z * x; a[cc].w += w4.w * x;
                        }
                    }
                }
#pragma unroll
                for (int cc = 0; cc < 4; cc++)
                    *(float4*)&PA[(ks * 4 + cc) * 64 + rq * 4] = a[cc];
            }
            BARW(1);
            {
                int ch = ta & 63, cc = ta >> 6;
                float s = 0;
#pragma unroll
                for (int ks = 0; ks < 16; ks++) s += PA[(ks * 4 + cc) * 64 + ch];
                out[ch * NPTS + (p0 + cc)] = s + bfc[ch];
            }
        }
    }
}

// ---------------- launch ----------------
extern "C" void kernel_launch(void* const* d_in, const int* in_sizes, int n_in,
                              void* d_out, int out_size) {
    const float* imf   = (const float*)d_in[0];
    const float* cloud = (const float*)d_in[1];
    const float* ctar  = (const float*)d_in[2];
    const float* w_conv1   = (const float*)d_in[3];
    const float* b_conv1   = (const float*)d_in[4];
    const float* w_conv2   = (const float*)d_in[5];
    const float* b_conv2   = (const float*)d_in[6];
    const float* w_psconv1 = (const float*)d_in[7];
    const float* b_psconv1 = (const float*)d_in[8];
    const float* w_psconv2 = (const float*)d_in[9];
    const float* b_psconv2 = (const float*)d_in[10];
    const float* w_pconv1  = (const float*)d_in[11];
    const float* b_pconv1  = (const float*)d_in[12];
    const float* w_pconv2  = (const float*)d_in[13];
    const float* b_pconv2  = (const float*)d_in[14];
    const float* w_fc1 = (const float*)d_in[15];
    const float* b_fc1 = (const float*)d_in[16];
    const float* w_fc2 = (const float*)d_in[17];
    const float* b_fc2 = (const float*)d_in[18];
    const float* w_fc  = (const float*)d_in[19];
    const float* b_fc  = (const float*)d_in[20];
    float* out = (float*)d_out;

    static bool attr_set = false;
    if (!attr_set) {
        cudaFuncSetAttribute(uber, cudaFuncAttributeMaxDynamicSharedMemorySize, SMF * 4);
        attr_set = true;
    }
    ktr<<<106, 256>>>(w_psconv2, w_conv2, w_fc1, w_fc2, w_fc, w_psconv1);
    uber<<<NBLK, 512, SMF * 4>>>(cloud, ctar, imf,
                                 w_pconv1, b_pconv1, w_pconv2, b_pconv2,
                                 w_conv1, b_conv1,
                                 b_psconv1, b_psconv2, b_conv2,
                                 b_fc1, b_fc2, b_fc,
                                 out);
}

// round 13
// speedup vs baseline: 1.1749x; 1.1749x over previous
#include <cuda_runtime.h>
#include <float.h>

#define NPTS 500
#define NP 8
#define NCOL 4000
#define NBLK 125

// ---------------- scratch (device globals) ----------------
__device__ int   g_inds[NCOL];
__device__ int   g_inds_tc[NCOL];
__device__ float g_expw[2 * NCOL];
__device__ float g_psum[1000];
__device__ float g_cf[NPTS * 128];
__device__ float g_imf[NPTS * 32];
__device__ float g_h1[NPTS * 64];
__device__ float g_hp[NPTS * 256];
__device__ float g_wps1T[128 * 256];
__device__ float g_wps2T[256 * 128];
__device__ float g_wc2T [64 * 128];
__device__ float g_wfc1T[256 * 64];
__device__ float g_wfc2T[160 * 64];
__device__ float g_wfcT [128 * 64];
// grid barrier + wps1T-ready counter: BOTH monotonic (graph-replay-safe)
__device__ unsigned          g_cnt = 0;
__device__ volatile unsigned g_gen = 0;
__device__ unsigned          g_done = 0;

__device__ __forceinline__ float lrelu(float x) { return x > 0.f ? x : 0.01f * x; }
__device__ __forceinline__ unsigned ordf(float f) {
    unsigned u = __float_as_uint(f);
    return (u & 0x80000000u) ? ~u : (u | 0x80000000u);
}
#define BARW(id) asm volatile("bar.sync %0, %1;" :: "r"(id), "r"(256) : "memory")

__device__ __forceinline__ void gbar() {
    __threadfence();
    __syncthreads();
    if (threadIdx.x == 0) {
        unsigned gen = g_gen;
        if (atomicAdd(&g_cnt, 1) == NBLK - 1) {
            g_cnt = 0;
            __threadfence();
            g_gen = gen + 1;
        } else {
            while (g_gen == gen) __nanosleep(32);
            __threadfence();
        }
    }
    __syncthreads();
}

#define SMF 14720

__global__ __launch_bounds__(512) void uber(
        const float* __restrict__ c,   const float* __restrict__ ct,
        const float* __restrict__ imf,
        const float* __restrict__ wp1, const float* __restrict__ bp1,
        const float* __restrict__ wp2, const float* __restrict__ bp2,
        const float* __restrict__ wc1, const float* __restrict__ bc1,
        const float* __restrict__ wps1, const float* __restrict__ bps1,
        const float* __restrict__ wps2, const float* __restrict__ bps2,
        const float* __restrict__ wc2,  const float* __restrict__ bc2,
        const float* __restrict__ wfc1, const float* __restrict__ bfc1,
        const float* __restrict__ wfc2, const float* __restrict__ bfc2,
        const float* __restrict__ wfc,  const float* __restrict__ bfc,
        float* __restrict__ out) {
    extern __shared__ __align__(16) float sm[];
    int t = threadIdx.x;
    int b = blockIdx.x;
    int p0 = b * 4;

    // ========================= P1 =========================
    if (t < 256) {
        // ---- KNN: 8 queries (warp/query), refs padded to 512 ----
        if (b <= 62) for (int i = t; i < 1536; i += 256) sm[i]        = (i < 1500) ? ct[i] : 1e18f;
        if (b >= 62) for (int i = t; i < 1536; i += 256) sm[1536 + i] = (i < 1500) ? c[i]  : 1e18f;
        BARW(1);

        int warp = t >> 5, lane = t & 31;
        int gw = b * 8 + warp;
        int dir = gw >= NPTS;
        int q = dir ? gw - NPTS : gw;
        const float* Qg = dir ? ct : c;
        float qx = __ldg(Qg + q * 3 + 0), qy = __ldg(Qg + q * 3 + 1), qz = __ldg(Qg + q * 3 + 2);
        float qq = qx * qx + qy * qy + qz * qz;

        const float* R = sm + (dir ? 1536 : 0);
        int j0 = lane * 16;
        float bd[8]; int bi[8];
#pragma unroll
        for (int k = 0; k < 8; k++) { bd[k] = FLT_MAX; bi[k] = 0x3fffffff; }

#pragma unroll
        for (int h8 = 0; h8 < 2; h8++) {
            float f[24];
            const float4* rp = (const float4*)(R + (j0 + h8 * 8) * 3);
#pragma unroll
            for (int v = 0; v < 6; v++) *(float4*)&f[v * 4] = rp[v];
#pragma unroll
            for (int jj = 0; jj < 8; jj++) {
                float rx = f[jj * 3 + 0], ry = f[jj * 3 + 1], rz = f[jj * 3 + 2];
                float d2 = qq - 2.f * (qx * rx + qy * ry + qz * rz) + (rx * rx + ry * ry + rz * rz);
                int j = j0 + h8 * 8 + jj;
                if (d2 < bd[7] || (d2 == bd[7] && j < bi[7])) {
                    bd[7] = d2; bi[7] = j;
#pragma unroll
                    for (int k = 7; k > 0; k--) {
                        if (bd[k] < bd[k - 1] || (bd[k] == bd[k - 1] && bi[k] < bi[k - 1])) {
                            float td = bd[k]; bd[k] = bd[k - 1]; bd[k - 1] = td;
                            int   ti = bi[k]; bi[k] = bi[k - 1]; bi[k - 1] = ti;
                        }
                    }
                }
            }
        }

        int* selS = (int*)(sm + 3072);
#pragma unroll
        for (int s = 0; s < NP; s++) {
            unsigned key = ordf(bd[0]);
            unsigned mk  = __reduce_min_sync(0xffffffffu, key);
            unsigned mask = __ballot_sync(0xffffffffu, key == mk);
            int owner = __ffs(mask) - 1;
            if (lane == owner) {
                selS[warp * 8 + s] = bi[0];
#pragma unroll
                for (int k = 0; k < 7; k++) { bd[k] = bd[k + 1]; bi[k] = bi[k + 1]; }
                bd[7] = FLT_MAX; bi[7] = 0x3fffffff;
            }
        }
        __syncwarp();

        int*   outi = dir ? g_inds_tc : g_inds;
        float* oute = dir ? (g_expw + NCOL) : g_expw;
        float e = 0.f;
        if (lane < NP) {
            int mi = selS[warp * 8 + lane];
            float dx = qx - R[mi * 3 + 0];
            float dy = qy - R[mi * 3 + 1];
            float dz = qz - R[mi * 3 + 2];
            e = expf(-sqrtf(dx * dx + dy * dy + dz * dz));
            outi[q * NP + lane] = mi;
            oute[q * NP + lane] = e;
        }
        if (lane < 8) {
            e += __shfl_xor_sync(0x000000ffu, e, 4);
            e += __shfl_xor_sync(0x000000ffu, e, 2);
            e += __shfl_xor_sync(0x000000ffu, e, 1);
            if (lane == 0) g_psum[gw] = e;
        }
    } else {
        // ---- features: transposes + 4 points (imf^T, H64, cf, h1, Hp) ----
        int t2 = t - 256;
        float* HS  = sm + 3200;           // [4][64]
        float* IS  = sm + 3456;           // [4][32]
        float* WC  = sm + 3584;           // [32][68]  wc1^T padded
        float* WT  = sm + 5760;           // [64][132] wp2^T padded; aliased: transpose S, Hp partials
        float* CFS = sm + 14208;          // [4][128]

        unsigned gen0 = 0;
        if (t2 == 0) gen0 = g_gen;        // launch index (read pre-gbar)

        // ---- transpose duty: blocks 0..31 -> wps1 tiles (signaled); 32..105 -> P3 weights
        if (b < 106) {
            const float* src; float* dst; int Rr, Cc, tile;
            if (b < 32) { src = wps1; dst = g_wps1T; Rr = 256; Cc = 128; tile = b; }
            else {
                int bb = b - 32;
                if      (bb < 32)  { src = wps2; dst = g_wps2T; Rr = 128; Cc = 256; tile = bb; }
                else if (bb < 40)  { src = wc2;  dst = g_wc2T;  Rr = 128; Cc = 64;  tile = bb - 32; }
                else if (bb < 56)  { src = wfc1; dst = g_wfc1T; Rr = 64;  Cc = 256; tile = bb - 40; }
                else if (bb < 66)  { src = wfc2; dst = g_wfc2T; Rr = 64;  Cc = 160; tile = bb - 56; }
                else               { src = wfc;  dst = g_wfcT;  Rr = 64;  Cc = 128; tile = bb - 66; }
            }
            int tilesC = Cc / 32;
            int tr = (tile / tilesC) * 32, tc = (tile % tilesC) * 32;
            float (*S)[33] = (float(*)[33])WT;
            int r = t2 >> 3, qd = t2 & 7;
            float4 v = *(const float4*)(src + (tr + r) * Cc + tc + qd * 4);
            S[r][qd * 4 + 0] = v.x; S[r][qd * 4 + 1] = v.y;
            S[r][qd * 4 + 2] = v.z; S[r][qd * 4 + 3] = v.w;
            BARW(2);
            float4 o;
            o.x = S[qd * 4 + 0][r]; o.y = S[qd * 4 + 1][r];
            o.z = S[qd * 4 + 2][r]; o.w = S[qd * 4 + 3][r];
            *(float4*)(dst + (tc + r) * Rr + tr + qd * 4) = o;
            if (b < 32) {
                __threadfence();
                BARW(2);
                if (t2 == 0) atomicAdd(&g_done, 1u);
            }
            BARW(2);   // S (=WT) dead; safe to re-stage below
        }

        for (int e = t2; e < 2048; e += 256) {        // wp2 -> WT[k][r]
            float4 v = __ldg((const float4*)(wp2 + e * 4));
            int r = e >> 4, k0 = (e & 15) * 4;
            WT[(k0 + 0) * 132 + r] = v.x;
            WT[(k0 + 1) * 132 + r] = v.y;
            WT[(k0 + 2) * 132 + r] = v.z;
            WT[(k0 + 3) * 132 + r] = v.w;
        }
        for (int e = t2; e < 512; e += 256) {         // wc1 -> WC[k][r]
            float4 v = __ldg((const float4*)(wc1 + e * 4));
            int r = e >> 3, k0 = (e & 7) * 4;
            WC[(k0 + 0) * 68 + r] = v.x;
            WC[(k0 + 1) * 68 + r] = v.y;
            WC[(k0 + 2) * 68 + r] = v.z;
            WC[(k0 + 3) * 68 + r] = v.w;
        }
        if (t2 < 128) {
            int lp = t2 >> 5, chn = t2 & 31;
            float v = imf[chn * NPTS + (p0 + lp)];
            IS[lp * 32 + chn] = v;
            g_imf[(p0 + lp) * 32 + chn] = v;
        }
        {
            int lp = t2 >> 6, r = t2 & 63;
            int p = p0 + lp;
            float h = bp1[r] + wp1[r * 3 + 0] * c[p * 3 + 0] + wp1[r * 3 + 1] * c[p * 3 + 1]
                             + wp1[r * 3 + 2] * c[p * 3 + 2];
            HS[lp * 64 + r] = lrelu(h);
        }
        BARW(2);

        if (t2 < 128) {   // cf: thread = (rowquad rq, point pt)
            int rq = t2 & 31, pt = t2 >> 5;
            const float* x = HS + pt * 64;
            float4 a = {0.f, 0.f, 0.f, 0.f};
#pragma unroll 8
            for (int k = 0; k < 64; k++) {
                float4 w = *(float4*)&WT[k * 132 + rq * 4];
                float xv = x[k];
                a.x += w.x * xv; a.y += w.y * xv; a.z += w.z * xv; a.w += w.w * xv;
            }
            float4 bb = __ldg((const float4*)(bp2 + rq * 4));
            a.x += bb.x; a.y += bb.y; a.z += bb.z; a.w += bb.w;
            *(float4*)&g_cf[(p0 + pt) * 128 + rq * 4] = a;
            *(float4*)&CFS[pt * 128 + rq * 4] = a;
        } else if (t2 < 192) {  // h1
            int u = t2 - 128, rq = u & 15, pt = u >> 4;
            const float* xi = IS + pt * 32;
            float4 a = {0.f, 0.f, 0.f, 0.f};
#pragma unroll 8
            for (int k = 0; k < 32; k++) {
                float4 w = *(float4*)&WC[k * 68 + rq * 4];
                float xv = xi[k];
                a.x += w.x * xv; a.y += w.y * xv; a.z += w.z * xv; a.w += w.w * xv;
            }
            float4 bb = __ldg((const float4*)(bc1 + rq * 4));
            float4 o;
            o.x = lrelu(a.x + bb.x); o.y = lrelu(a.y + bb.y);
            o.z = lrelu(a.z + bb.z); o.w = lrelu(a.w + bb.w);
            *(float4*)&g_h1[(p0 + pt) * 64 + rq * 4] = o;
        }

        // ---- wait for wps1T (monotonic target; usually already satisfied) ----
        if (t2 == 0) {
            unsigned target = 32u * (gen0 + 1u);
            while (*(volatile unsigned*)&g_done < target) __nanosleep(32);
        }
        BARW(2);

        {   // Hp: 256 rows x 4 cols, K=128; 256 threads: rq=t2&63, ks=t2>>6 (4 x K=32)
            float* P = WT;     // alias, WT dead after cf
            int rq = t2 & 63, ks = t2 >> 6;
            float4 a[4] = {};
            const float* wp = g_wps1T + (ks * 32) * 256 + rq * 4;
#pragma unroll
            for (int kg = 0; kg < 8; kg++) {
                float xk[4][4];
#pragma unroll
                for (int cc = 0; cc < 4; cc++)
                    *(float4*)xk[cc] = *(float4*)&CFS[cc * 128 + ks * 32 + kg * 4];
#pragma unroll
                for (int j = 0; j < 4; j++) {
                    float4 w4 = *(const float4*)(wp + (kg * 4 + j) * 256);
#pragma unroll
                    for (int cc = 0; cc < 4; cc++) {
                        float x = xk[cc][j];
                        a[cc].x += w4.x * x; a[cc].y += w4.y * x; a[cc].z += w4.z * x; a[cc].w += w4.w * x;
                    }
                }
            }
#pragma unroll
            for (int cc = 0; cc < 4; cc++)
                *(float4*)&P[(ks * 4 + cc) * 256 + rq * 4] = a[cc];
            BARW(2);
            for (int o = t2; o < 1024; o += 256) {
                int r = o & 255, cc2 = o >> 8;
                float s = 0.f;
#pragma unroll
                for (int k2 = 0; k2 < 4; k2++) s += P[(k2 * 4 + cc2) * 256 + r];
                g_hp[(p0 + cc2) * 256 + r] = lrelu(s + bps1[r]);
            }
        }
    }
    gbar();

    // ========================= P3: denom + gathers + GEMM chain =========================
    {
        int*   I0  = (int*)(sm + 0);
        int*   I1  = (int*)(sm + 32);
        float* W0  = sm + 64;
        float* W1  = sm + 96;
        float* Ws0 = sm + 128;
        float* Ws1 = sm + 132;
        float* Hb  = sm + 136;    // [4][64]
        float* Hpb = sm + 392;    // [4][256]
        float* A1  = sm + 1416;   // [4][256]  low=Sf high=Cf
        float* A2  = sm + 2440;   // [4][160]  low=Sfp high=Im
        float* Z   = sm + 3080;   // [4][128]
        float* PA  = sm + 3592;   // 4096
        float* PB  = sm + 7688;   // 4096
        float* RED = sm + 12900;  // [2][16]

        int wg = t >> 8, ta = t & 255;

        {
            float v0 = (t < 500) ? g_psum[t]       : 0.f;
            float v1 = (t < 500) ? g_psum[500 + t] : 0.f;
#pragma unroll
            for (int off = 16; off; off >>= 1) {
                v0 += __shfl_xor_sync(0xffffffffu, v0, off);
                v1 += __shfl_xor_sync(0xffffffffu, v1, off);
            }
            if ((t & 31) == 0) { RED[t >> 5] = v0; RED[32 + (t >> 5)] = v1; }
        }
        if (wg == 0) {
            if (ta < 32) {
                int e = p0 * NP + ta;
                I0[ta] = g_inds[e];    W0[ta] = g_expw[e];
                I1[ta] = g_inds_tc[e]; W1[ta] = g_expw[NCOL + e];
            } else if (ta < 64) {
                int tt = ta - 32;
                int col = tt >> 3, f = tt & 7;
                *(float4*)&A2[col * 160 + 128 + f * 4] = *(const float4*)&g_imf[(p0 + col) * 32 + f * 4];
            }
        } else {
            if (ta < 128) {
                int col = ta >> 5, f = ta & 31;
                *(float4*)&A1[col * 256 + 128 + f * 4] = *(const float4*)&g_cf[(p0 + col) * 128 + f * 4];
            }
        }
        __syncthreads();
        if (t == 0) {
            float s0 = 0.f, s1 = 0.f;
#pragma unroll
            for (int w = 0; w < 16; w++) { s0 += RED[w]; s1 += RED[32 + w]; }
            sm[13000] = 1.f / s0;
            sm[13001] = 1.f / s1;
        }
        __syncthreads();
        float inv0 = sm[13000], inv1 = sm[13001];

        if (wg == 0) {
            if (ta < 4) {
                float s = 0;
#pragma unroll
                for (int j = 0; j < 8; j++) s += W1[ta * 8 + j];
                Ws1[ta] = 0.125f * inv1 * s;
            }
            {
                int r = ta;
#pragma unroll
                for (int lp = 0; lp < 4; lp++) {
                    float s = 0;
#pragma unroll
                    for (int j = 0; j < 8; j++) s += W1[lp * 8 + j] * g_hp[I1[lp * 8 + j] * 256 + r];
                    Hpb[lp * 256 + r] = 0.125f * inv1 * s;
                }
            }
            BARW(1);
            {   // Y2: 128 rows, K=256
                int rq = ta & 31, ks = ta >> 5;
                float4 a[4] = {};
                const float* wp = g_wps2T + (ks * 32) * 128 + rq * 4;
#pragma unroll
                for (int kg = 0; kg < 8; kg++) {
                    float xk[4][4];
#pragma unroll
                    for (int cc = 0; cc < 4; cc++)
                        *(float4*)xk[cc] = *(float4*)&Hpb[cc * 256 + ks * 32 + kg * 4];
#pragma unroll
                    for (int j = 0; j < 4; j++) {
                        float4 w4 = *(const float4*)(wp + (kg * 4 + j) * 128);
#pragma unroll
                        for (int cc = 0; cc < 4; cc++) {
                            float x = xk[cc][j];
                            a[cc].x += w4.x * x; a[cc].y += w4.y * x; a[cc].z += w4.z * x; a[cc].w += w4.w * x;
                        }
                    }
                }
#pragma unroll
                for (int cc = 0; cc < 4; cc++)
                    *(float4*)&PA[(ks * 4 + cc) * 128 + rq * 4] = a[cc];
            }
            BARW(1);
            for (int o = ta; o < 512; o += 256) {
                int r = o & 127, cc = o >> 7;
                float s = 0;
#pragma unroll
                for (int ks = 0; ks < 8; ks++) s += PA[(ks * 4 + cc) * 128 + r];
                A2[cc * 160 + r] = s + bps2[r] * Ws1[cc];
            }
            BARW(1);
            {   // f2: 64 rows, K=160
                int rq = ta & 15, ks = ta >> 4;
                float4 a[4] = {};
                const float* wp = g_wfc2T + (ks * 10) * 64 + rq * 4;
#pragma unroll
                for (int k = 0; k < 10; k++) {
                    float4 w4 = *(const float4*)(wp + k * 64);
                    int kk = ks * 10 + k;
#pragma unroll
                    for (int cc = 0; cc < 4; cc++) {
                        float x = A2[cc * 160 + kk];
                        a[cc].x += w4.x * x; a[cc].y += w4.y * x; a[cc].z += w4.z * x; a[cc].w += w4.w * x;
                    }
                }
#pragma unroll
                for (int cc = 0; cc < 4; cc++)
                    *(float4*)&PA[(ks * 4 + cc) * 64 + rq * 4] = a[cc];
            }
            BARW(1);
            {
                int ch = ta & 63, cc = ta >> 6;
                float s = 0;
#pragma unroll
                for (int ks = 0; ks < 16; ks++) s += PA[(ks * 4 + cc) * 64 + ch];
                Z[cc * 128 + ch] = lrelu(s + bfc2[ch]);
            }
        } else {
            if (ta < 4) {
                float s = 0;
#pragma unroll
                for (int j = 0; j < 8; j++) s += W0[ta * 8 + j];
                Ws0[ta] = 0.125f * inv0 * s;
            }
            {
                int lp = ta >> 6, r = ta & 63;
                float s = 0;
#pragma unroll
                for (int j = 0; j < 8; j++) s += W0[lp * 8 + j] * g_h1[I0[lp * 8 + j] * 64 + r];
                Hb[lp * 64 + r] = 0.125f * inv0 * s;
            }
            BARW(2);
            {   // Y1: 128 rows, K=64
                int rq = ta & 31, ks = ta >> 5;
                float4 a[4] = {};
                const float* wp = g_wc2T + (ks * 8) * 128 + rq * 4;
#pragma unroll
                for (int kg = 0; kg < 2; kg++) {
                    float xk[4][4];
#pragma unroll
                    for (int cc = 0; cc < 4; cc++)
                        *(float4*)xk[cc] = *(float4*)&Hb[cc * 64 + ks * 8 + kg * 4];
#pragma unroll
                    for (int j = 0; j < 4; j++) {
                        float4 w4 = *(const float4*)(wp + (kg * 4 + j) * 128);
#pragma unroll
                        for (int cc = 0; cc < 4; cc++) {
                            float x = xk[cc][j];
                            a[cc].x += w4.x * x; a[cc].y += w4.y * x; a[cc].z += w4.z * x; a[cc].w += w4.w * x;
                        }
                    }
                }
#pragma unroll
                for (int cc = 0; cc < 4; cc++)
                    *(float4*)&PB[(ks * 4 + cc) * 128 + rq * 4] = a[cc];
            }
            BARW(2);
            for (int o = ta; o < 512; o += 256) {
                int r = o & 127, cc = o >> 7;
                float s = 0;
#pragma unroll
                for (int ks = 0; ks < 8; ks++) s += PB[(ks * 4 + cc) * 128 + r];
                A1[cc * 256 + r] = s + bc2[r] * Ws0[cc];
            }
            BARW(2);
            {   // f1: 64 rows, K=256
                int rq = ta & 15, ks = ta >> 4;
                float4 a[4] = {};
                const float* wp = g_wfc1T + (ks * 16) * 64 + rq * 4;
#pragma unroll
                for (int kg = 0; kg < 4; kg++) {
                    float xk[4][4];
#pragma unroll
                    for (int cc = 0; cc < 4; cc++)
                        *(float4*)xk[cc] = *(float4*)&A1[cc * 256 + ks * 16 + kg * 4];
#pragma unroll
                    for (int j = 0; j < 4; j++) {
                        float4 w4 = *(const float4*)(wp + (kg * 4 + j) * 64);
#pragma unroll
                        for (int cc = 0; cc < 4; cc++) {
                            float x = xk[cc][j];
                            a[cc].x += w4.x * x; a[cc].y += w4.y * x; a[cc].z += w4.z * x; a[cc].w += w4.w * x;
                        }
                    }
                }
#pragma unroll
                for (int cc = 0; cc < 4; cc++)
                    *(float4*)&PB[(ks * 4 + cc) * 64 + rq * 4] = a[cc];
            }
            BARW(2);
            {
                int ch = ta & 63, cc = ta >> 6;
                float s = 0;
#pragma unroll
                for (int ks = 0; ks < 16; ks++) s += PB[(ks * 4 + cc) * 64 + ch];
                Z[cc * 128 + 64 + ch] = lrelu(s + bfc1[ch]);
            }
        }
        __syncthreads();

        if (wg == 0) {
            {   // out: 64 rows, K=128
                int rq = ta & 15, ks = ta >> 4;
                float4 a[4] = {};
                const float* wp = g_wfcT + (ks * 8) * 64 + rq * 4;
#pragma unroll
                for (int kg = 0; kg < 2; kg++) {
                    float xk[4][4];
#pragma unroll
                    for (int cc = 0; cc < 4; cc++)
                        *(float4*)xk[cc] = *(float4*)&Z[cc * 128 + ks * 8 + kg * 4];
#pragma unroll
                    for (int j = 0; j < 4; j++) {
                        float4 w4 = *(const float4*)(wp + (kg * 4 + j) * 64);
#pragma unroll
                        for (int cc = 0; cc < 4; cc++) {
                            float x = xk[cc][j];
                            a[cc].x += w4.x * x; a[cc].y += w4.y * x; a[cc].z += w4.z * x; a[cc].w += w4.w * x;
                        }
                    }
                }
#pragma unroll
                for (int cc = 0; cc < 4; cc++)
                    *(float4*)&PA[(ks * 4 + cc) * 64 + rq * 4] = a[cc];
            }
            BARW(1);
            {
                int ch = ta & 63, cc = ta >> 6;
                float s = 0;
#pragma unroll
                for (int ks = 0; ks < 16; ks++) s += PA[(ks * 4 + cc) * 64 + ch];
                out[ch * NPTS + (p0 + cc)] = s + bfc[ch];
            }
        }
    }
}

// ---------------- launch ----------------
extern "C" void kernel_launch(void* const* d_in, const int* in_sizes, int n_in,
                              void* d_out, int out_size) {
    const float* imf   = (const float*)d_in[0];
    const float* cloud = (const float*)d_in[1];
    const float* ctar  = (const float*)d_in[2];
    const float* w_conv1   = (const float*)d_in[3];
    const float* b_conv1   = (const float*)d_in[4];
    const float* w_conv2   = (const float*)d_in[5];
    const float* b_conv2   = (const float*)d_in[6];
    const float* w_psconv1 = (const float*)d_in[7];
    const float* b_psconv1 = (const float*)d_in[8];
    const float* w_psconv2 = (const float*)d_in[9];
    const float* b_psconv2 = (const float*)d_in[10];
    const float* w_pconv1  = (const float*)d_in[11];
    const float* b_pconv1  = (const float*)d_in[12];
    const float* w_pconv2  = (const float*)d_in[13];
    const float* b_pconv2  = (const float*)d_in[14];
    const float* w_fc1 = (const float*)d_in[15];
    const float* b_fc1 = (const float*)d_in[16];
    const float* w_fc2 = (const float*)d_in[17];
    const float* b_fc2 = (const float*)d_in[18];
    const float* w_fc  = (const float*)d_in[19];
    const float* b_fc  = (const float*)d_in[20];
    float* out = (float*)d_out;

    static bool attr_set = false;
    if (!attr_set) {
        cudaFuncSetAttribute(uber, cudaFuncAttributeMaxDynamicSharedMemorySize, SMF * 4);
        attr_set = true;
    }
    uber<<<NBLK, 512, SMF * 4>>>(cloud, ctar, imf,
                                 w_pconv1, b_pconv1, w_pconv2, b_pconv2,
                                 w_conv1, b_conv1,
                                 w_psconv1, b_psconv1,
                                 w_psconv2, b_psconv2,
                                 w_conv2, b_conv2,
                                 w_fc1, b_fc1, w_fc2, b_fc2, w_fc, b_fc,
                                 out);
}